// round 15
// baseline (speedup 1.0000x reference)
#include <cuda_runtime.h>

#define TS  50
#define BB  512
#define NE  400
#define NIN 784
#define BE  (BB*NE)
#define BI  (BB*NIN)
#define WSZ (NE*NIN)
#define ADS 896            // a1d/a2d row stride (dup 800 + zero pad)
#define XPS 832            // xp/trpP row stride (784 + zero pad)
#define NBLK 296
#define GZ  5
#define SZ  3
#define NG  280   // G blocks (7e x 8b x 5z)
#define NN  256   // N blocks (512 batches / 2)
#define NS  273   // S blocks (13i x 7e x 3z)

#define WS_STRIDE 164
#define SM_AS     10496                 // G: Ws = 64*164 floats, then As 2*1280
#define SMEM_FLOATS 13056
#define SMEM_BYTES  (SMEM_FLOATS*4 + 256)

typedef unsigned long long u64;

// ---------------- f32x2 helpers ----------------
__device__ __forceinline__ u64 fma2(u64 a, u64 b, u64 c) {
    u64 d;
    asm("fma.rn.f32x2 %0, %1, %2, %3;" : "=l"(d) : "l"(a), "l"(b), "l"(c));
    return d;
}
__device__ __forceinline__ float2 upk2(u64 v) {
    float2 u; asm("mov.b64 {%0, %1}, %2;" : "=f"(u.x), "=f"(u.y) : "l"(v)); return u;
}

// ---------------- persistent device state ----------------
__device__ float g_Wbuf[2 * WSZ];          // double-buffered W carry
__device__ float g_rsp[2 * 13 * 400];      // row-sum partials [buf][ix][e]
__device__ float g_sc[2 * 400];            // scale 78.4/rowsum per buf
__device__ float g_dw[SZ * WSZ];
__device__ float g_dg[GZ * BE];            // UNSCALED dg partials
__device__ float g_gine[BE], g_gei[BE], g_gie[BE], g_Iie[BE];
__device__ float g_meme[BE], g_rce[BE], g_memi[BE], g_rci[BE];
__device__ float g_theta[BE], g_tp1[BE], g_tp2[BE];
__device__ float g_a1d[BB * ADS];          // duplicated (v,v) pairs, zero tails
__device__ float g_a2d[BB * ADS];
__device__ float g_xp[BB * XPS];           // padded x mirror (per step)
__device__ float g_trpP[BB * XPS];         // padded trace_pre

// ---------------- dataflow flags (cumulative; zeroed in init) ----------------
__device__ unsigned g_gflag[8 * 32];    // per b-tile: G arrivals (35/step)
__device__ unsigned g_nflag[8 * 32];    // per b-tile: N arrivals (32/step)
__device__ unsigned g_sflag[3 * 32];    // per z: S arrivals (91/step)
__device__ unsigned g_wcnt[91 * 8];     // per (ey,ix): S z arrivals (3/step)
__device__ unsigned g_wtile[91 * 8];    // per tile: finalizer done (1/step)
__device__ unsigned g_wey[7 * 32];      // per e-tile: 13 finalizers + 1 scale (14/step)

// ---------------- one-time grid barrier (init only) ----------------
__device__ unsigned g_count;
__device__ unsigned g_gen;
__device__ __forceinline__ void gbar() {
    __syncthreads();
    if (threadIdx.x == 0) {
        __threadfence();
        unsigned gen = *(volatile unsigned*)&g_gen;
        if (atomicAdd(&g_count, 1u) == NBLK - 1) {
            g_count = 0;
            __threadfence();
            *(volatile unsigned*)&g_gen = gen + 1;
        } else {
            while (*(volatile unsigned*)&g_gen == gen) { __nanosleep(40); }
        }
        __threadfence();
    }
    __syncthreads();
}

#define POLL_GE(addr, tgt) do { while (*(volatile unsigned*)(addr) < (tgt)) {} } while (0)

__device__ __forceinline__ void acq() {
    __syncthreads();
    if (threadIdx.x == 0) __threadfence();
    __syncthreads();
}

// ---------------- neuron state update ----------------
__device__ __forceinline__ void neuron_update(int b, int e, float scl, float wei_diag,
                                              float* __restrict__ out, size_t out_off,
                                              float& s_i_out, float& gie_old_out, float& meme_out) {
    int idx = b * NE + e;
    float dg = __fmul_rn(g_dg[idx], scl);
#pragma unroll
    for (int z = 1; z < GZ; z++) dg = __fadd_rn(dg, __fmul_rn(g_dg[z * BE + idx], scl));
    float gine = g_gine[idx];
    float meme = g_meme[idx];
    float Iie = g_Iie[idx];
    float Iine = gine * (0.f - meme);                 // E_EE = 0
    gine += (dg - gine) * 0.5f;                        // DT/TAU_SYN_E
    g_gine[idx] = gine;
    float theta = g_theta[idx];
    float thr = -52.f - 20.f + theta;
    float rce = g_rce[idx];
    bool act = (rce <= 0.f);
    if (act) meme += (-65.f - meme + (Iine + Iie)) * 0.005f;   // DT/TAU_MEM_E
    rce = fmaxf(rce - 0.5f, 0.f);
    float s = (act && meme > thr) ? 1.f : 0.f;
    if (s > 0.f) { meme = -65.f; rce = 5.f; }
    g_meme[idx] = meme; g_rce[idx] = rce;
    float dgei = s * wei_diag;
    float gei = g_gei[idx];
    float memi = g_memi[idx];
    float Iei = gei * (0.f - memi);                   // E_EI = 0
    gei += (dgei - gei) * 0.5f;
    g_gei[idx] = gei;
    float rci = g_rci[idx];
    bool acti = (rci <= 0.f);
    if (acti) memi += (-60.f - memi + Iei) * 0.05f;   // DT/TAU_MEM_I
    rci = fmaxf(rci - 0.5f, 0.f);
    float s_i = (acti && memi > -40.f) ? 1.f : 0.f;
    if (s_i > 0.f) { memi = -45.f; rci = 2.f; }
    g_memi[idx] = memi; g_rci[idx] = rci;
    theta = theta * (1.0f - 0.5f / 1e7f) + 0.05f * s;
    g_theta[idx] = theta;
    float tp1 = g_tp1[idx], tp2 = g_tp2[idx];
    float r1 = tp1 * (1.0f - 0.5f / 20.0f);
    float r2 = tp2 * (1.0f - 0.5f / 40.0f);
    bool fired = (s > 0.9f);
    g_tp1[idx] = fired ? 1.f : r1;
    g_tp2[idx] = fired ? 1.f : r2;
    float a1v = 1e-4f * r1;                           // NU_PRE folded
    float a2v = fired ? 0.01f * r2 : 0.f;             // NU_POST * spike * ret2
    *(float2*)&g_a1d[(size_t)b * ADS + 2 * e] = make_float2(a1v, a1v);
    *(float2*)&g_a2d[(size_t)b * ADS + 2 * e] = make_float2(a2v, a2v);
    out[out_off + idx] = s;
    s_i_out = s_i; gie_old_out = g_gie[idx]; meme_out = meme;
}

// ---------------- the single persistent dataflow kernel ----------------
__global__ void __launch_bounds__(256, 2) k_persist(const float* __restrict__ x,
                                                    const float* __restrict__ Wei,
                                                    const float* __restrict__ Wie,
                                                    const float* __restrict__ Wine,
                                                    float* __restrict__ out) {
    extern __shared__ __align__(16) float smem[];
    __shared__ unsigned s_fin, s_is13;
    const int bid = blockIdx.x, tid = threadIdx.x;
    const int gtid = bid * 256 + tid;
    const int sub = tid >> 7;
    const int stid = tid & 127;
    const float4 f4z = make_float4(0.f, 0.f, 0.f, 0.f);

    // ---- INIT ----
    for (int i = gtid; i < BB * ADS; i += NBLK * 256) {
        g_a1d[i] = 0.f; g_a2d[i] = 0.f;
        if (i < BB * XPS) { g_xp[i] = 0.f; g_trpP[i] = 0.f; }
        if (i < WSZ) g_Wbuf[i] = Wine[i];          // buffer 0 = Wc(0)
        if (i < BE) {
            g_gine[i] = 0.f; g_gei[i] = 0.f; g_gie[i] = 0.f; g_Iie[i] = 0.f;
            g_meme[i] = -65.f; g_rce[i] = 0.f;
            g_memi[i] = -60.f; g_rci[i] = 0.f;
            g_theta[i] = 20.f; g_tp1[i] = 0.f; g_tp2[i] = 0.f;
        }
        if (i >= 400 && i < 5200) g_rsp[i] = 0.f;  // buf0, ix 1..12 -> 0
        if (i < 8 * 32)  { g_gflag[i] = 0u; g_nflag[i] = 0u; }
        if (i < 3 * 32)  g_sflag[i] = 0u;
        if (i < 91 * 8)  { g_wcnt[i] = 0u; g_wtile[i] = 0u; }
        if (i < 7 * 32)  g_wey[i] = 0u;
    }
    // exact row-sums of Wine -> g_rsp[buf0][ix=0][e], and g_sc[buf0]
    if (bid < 200) {
        int e = bid * 2 + sub;
        float sum = 0.f;
        if (e < NE) {
            const float* row = Wine + e * NIN;
            for (int i = stid; i < NIN; i += 128) sum += row[i];
        }
        for (int o = 16; o > 0; o >>= 1) sum += __shfl_down_sync(0xffffffffu, sum, o);
        if ((tid & 31) == 0) smem[tid >> 5] = sum;
        __syncthreads();
        if (stid == 0 && e < NE) {
            float rs = smem[sub * 4] + smem[sub * 4 + 1] + smem[sub * 4 + 2] + smem[sub * 4 + 3];
            g_rsp[e] = rs;
            g_sc[e] = 78.4f / rs;
        }
    }
    gbar();

    const float wie = Wie[1];    // uniform off-diagonal (17.0)

    for (int t = 0; t < TS; t++) {
        const float* xt = x + (size_t)t * BI;
        const int p = t & 1;
        const unsigned ut = (unsigned)t;

        // ================= G role: dg_z[b,e] = sum_k x[b,k]*Wc[e,k] =================
        if (bid < NG) {
            int z = bid / 56, r = bid % 56;
            int ex = r % 7, by = r / 7;
            int e0 = ex * 64, b0 = by * 64;
            int kz = z * 160;
            int nk = (z == GZ - 1) ? 9 : 10;
            if (tid == 0)  POLL_GE(&g_nflag[by * 32], 32u * ut);
            if (tid == 32) POLL_GE(&g_wey[ex * 32], 14u * ut);
            acq();

            float* Ws = smem;                           // [64][WS_STRIDE]
            float* As = smem + SM_AS;                   // [2][64][20]
            int lrow = tid >> 2, lk4 = (tid & 3) * 4;
            int e = e0 + lrow;
            bool eok = e < NE;
            const float* Wc = g_Wbuf + p * WSZ;
            float4 xreg = *(const float4*)&xt[(b0 + lrow) * NIN + kz + lk4];
#pragma unroll 5
            for (int c = 0; c < nk; c++) {
                int kg = kz + c * 16 + lk4;
                *(float4*)&Ws[lrow * WS_STRIDE + c * 16 + lk4] =
                    eok ? *(const float4*)&Wc[e * NIN + kg] : f4z;
            }

            int tx = tid & 15, ty = tid >> 4;
            u64 acc[4][4];
#pragma unroll
            for (int jm = 0; jm < 4; jm++)
#pragma unroll
                for (int jn = 0; jn < 4; jn++) acc[jm][jn] = 0ULL;

            for (int c = 0; c < nk; c++) {
                float* Ab = As + (c & 1) * 1280;
                *(float4*)&Ab[lrow * 20 + lk4] = xreg;
                __syncthreads();
                if (c + 1 < nk)
                    xreg = *(const float4*)&xt[(b0 + lrow) * NIN + kz + (c + 1) * 16 + lk4];
#pragma unroll
                for (int kk = 0; kk < 16; kk += 4) {
                    ulonglong2 ap[4], bp[4];
#pragma unroll
                    for (int jm = 0; jm < 4; jm++)
                        ap[jm] = *(const ulonglong2*)&Ab[(ty + 16 * jm) * 20 + kk];
#pragma unroll
                    for (int jn = 0; jn < 4; jn++)
                        bp[jn] = *(const ulonglong2*)&Ws[(tx + 16 * jn) * WS_STRIDE + c * 16 + kk];
#pragma unroll
                    for (int jm = 0; jm < 4; jm++)
#pragma unroll
                        for (int jn = 0; jn < 4; jn++) {
                            acc[jm][jn] = fma2(ap[jm].x, bp[jn].x, acc[jm][jn]);
                            acc[jm][jn] = fma2(ap[jm].y, bp[jn].y, acc[jm][jn]);
                        }
                }
            }
            float* dg = g_dg + z * BE;
#pragma unroll
            for (int jn = 0; jn < 4; jn++) {
                int ee = e0 + tx + 16 * jn;
                if (ee < NE) {
#pragma unroll
                    for (int jm = 0; jm < 4; jm++) {
                        float2 u = upk2(acc[jm][jn]);
                        dg[(b0 + ty + 16 * jm) * NE + ee] = u.x + u.y;
                    }
                }
            }
            __syncthreads();
            if (tid == 0) { __threadfence(); atomicAdd(&g_gflag[by * 32], 1u); }
        }

        // ================= N role: neuron dynamics for batches 2bid, 2bid+1 =================
        if (bid < NN) {
            int btile = bid >> 5;
            int zb = (2 * bid < 176) ? 0 : ((2 * bid < 352) ? 1 : 2);
            if (tid < 7) {
                POLL_GE(&g_wey[tid * 32], 14u * ut);
            } else if (tid == 8) {
                POLL_GE(&g_gflag[btile * 32], 35u * (ut + 1u));
            } else if (tid == 9) {
                POLL_GE(&g_sflag[zb * 32], 91u * ut);
            }
            acq();

            const float* sc = g_sc + p * 400;
            int b = bid * 2 + sub;
            float s_i[4], gie_o[4], mem_n[4];
            float ssum = 0.f;
#pragma unroll
            for (int j = 0; j < 4; j++) { s_i[j] = 0.f; gie_o[j] = 0.f; mem_n[j] = 0.f; }
#pragma unroll
            for (int j = 0; j < 4; j++) {
                int e = stid + j * 128;
                if (e < NE) {
                    neuron_update(b, e, sc[e], Wei[e * NE + e], out, (size_t)t * BE,
                                  s_i[j], gie_o[j], mem_n[j]);
                    ssum += s_i[j];
                }
            }
            for (int o = 16; o > 0; o >>= 1) ssum += __shfl_down_sync(0xffffffffu, ssum, o);
            if ((tid & 31) == 0) smem[tid >> 5] = ssum;
            __syncthreads();
            if (tid == 0)   smem[8] = smem[0] + smem[1] + smem[2] + smem[3];
            if (tid == 128) smem[9] = smem[4] + smem[5] + smem[6] + smem[7];
            __syncthreads();
            float S = smem[8 + sub];
#pragma unroll
            for (int j = 0; j < 4; j++) {
                int e = stid + j * 128;
                if (e < NE) {
                    int idx = b * NE + e;
                    float dgie = wie * (S - s_i[j]);
                    g_Iie[idx] = gie_o[j] * (-100.f - mem_n[j]);
                    g_gie[idx] = gie_o[j] + (dgie - gie_o[j]) * 0.25f;
                }
            }
            const float* xr = xt + (size_t)b * NIN;
            float* xpd = g_xp + (size_t)b * XPS;
            float* trp = g_trpP + (size_t)b * XPS;
            if (t == 0) {
                for (int i = stid; i < NIN; i += 128) { float xv = xr[i]; xpd[i] = xv; trp[i] = xv; }
            } else {
                for (int i = stid; i < NIN; i += 128) {
                    float xv = xr[i];
                    xpd[i] = xv;
                    trp[i] = (xv > 0.9f) ? 1.f : trp[i] * (1.0f - 0.5f / 20.0f);
                }
            }
            __syncthreads();
            if (tid == 0) { __threadfence(); atomicAdd(&g_nflag[btile * 32], 1u); }
        }

        // ================= S role: dw_z partial + (last z) W finalize =================
        if (bid < NS) {
            int z = bid / 91, r = bid % 91;
            int ix = r % 13, ey = r / 13;
            int tile = ey * 13 + ix;
            int i0 = ix * 64, e0 = ey * 64;
            int bz = z * 176;
            int nkt = (z == SZ - 1) ? 10 : 11;
            const int s_t0 = (z == 0) ? 0 : ((z == 1) ? 2 : 5);
            const int s_tc = (z == 1) ? 4 : 3;
            if (tid < s_tc) {
                POLL_GE(&g_nflag[(s_t0 + tid) * 32], 32u * (ut + 1u));
            } else if (tid == 8) {
                POLL_GE(&g_wtile[tile * 8], ut);
            }
            acq();

            // smem: A1d [16][132]f, A2d [16][132]f, X [16][68]f, T [16][68]f
            float* A1s = smem;                 // 2112 floats
            float* A2s = smem + 2112;          // 2112
            float* Xs  = smem + 4224;          // 1088
            float* Ts  = smem + 5312;          // 1088
            int tx = tid & 15, ty = tid >> 4;
            int lrow = tid >> 4;               // k row 0..15
            int lc   = tid & 15;               // column chunk

            u64 acc[4][2];
#pragma unroll
            for (int jm = 0; jm < 4; jm++) { acc[jm][0] = 0ULL; acc[jm][1] = 0ULL; }

            // prefetch chunk 0 (all sources zero-padded -> unguarded)
            int kb0 = bz + lrow;
            const float* a1p_ = g_a1d + (size_t)kb0 * ADS + 2 * e0 + lc * 8;
            const float* a2p_ = g_a2d + (size_t)kb0 * ADS + 2 * e0 + lc * 8;
            float4 p1a = *(const float4*)a1p_;
            float4 p1b = *(const float4*)(a1p_ + 4);
            float4 p2a = *(const float4*)a2p_;
            float4 p2b = *(const float4*)(a2p_ + 4);
            float4 pxv = *(const float4*)&g_xp[(size_t)kb0 * XPS + i0 + lc * 4];
            float4 ptv = *(const float4*)&g_trpP[(size_t)kb0 * XPS + i0 + lc * 4];

            for (int kt = 0; kt < nkt; kt++) {
                *(float4*)&A1s[lrow * 132 + lc * 8]     = p1a;
                *(float4*)&A1s[lrow * 132 + lc * 8 + 4] = p1b;
                *(float4*)&A2s[lrow * 132 + lc * 8]     = p2a;
                *(float4*)&A2s[lrow * 132 + lc * 8 + 4] = p2b;
                *(float4*)&Xs[lrow * 68 + lc * 4] = pxv;
                *(float4*)&Ts[lrow * 68 + lc * 4] = ptv;
                __syncthreads();
                if (kt + 1 < nkt) {
                    int kb = bz + (kt + 1) * 16 + lrow;
                    const float* a1n = g_a1d + (size_t)kb * ADS + 2 * e0 + lc * 8;
                    const float* a2n = g_a2d + (size_t)kb * ADS + 2 * e0 + lc * 8;
                    p1a = *(const float4*)a1n;
                    p1b = *(const float4*)(a1n + 4);
                    p2a = *(const float4*)a2n;
                    p2b = *(const float4*)(a2n + 4);
                    pxv = *(const float4*)&g_xp[(size_t)kb * XPS + i0 + lc * 4];
                    ptv = *(const float4*)&g_trpP[(size_t)kb * XPS + i0 + lc * 4];
                }
                const u64* A1u = (const u64*)A1s;
                const u64* A2u = (const u64*)A2s;
                const u64* Xu  = (const u64*)Xs;
                const u64* Tu  = (const u64*)Ts;
#pragma unroll
                for (int k = 0; k < 16; k++) {
                    ulonglong2 a1p = *(const ulonglong2*)&A1u[k * 66 + ty * 4];
                    ulonglong2 a1q = *(const ulonglong2*)&A1u[k * 66 + ty * 4 + 2];
                    ulonglong2 a2p = *(const ulonglong2*)&A2u[k * 66 + ty * 4];
                    ulonglong2 a2q = *(const ulonglong2*)&A2u[k * 66 + ty * 4 + 2];
                    ulonglong2 xp = *(const ulonglong2*)&Xu[k * 34 + tx * 2];
                    ulonglong2 tq = *(const ulonglong2*)&Tu[k * 34 + tx * 2];
                    acc[0][0] = fma2(a1p.x, xp.x, acc[0][0]);
                    acc[0][0] = fma2(a2p.x, tq.x, acc[0][0]);
                    acc[0][1] = fma2(a1p.x, xp.y, acc[0][1]);
                    acc[0][1] = fma2(a2p.x, tq.y, acc[0][1]);
                    acc[1][0] = fma2(a1p.y, xp.x, acc[1][0]);
                    acc[1][0] = fma2(a2p.y, tq.x, acc[1][0]);
                    acc[1][1] = fma2(a1p.y, xp.y, acc[1][1]);
                    acc[1][1] = fma2(a2p.y, tq.y, acc[1][1]);
                    acc[2][0] = fma2(a1q.x, xp.x, acc[2][0]);
                    acc[2][0] = fma2(a2q.x, tq.x, acc[2][0]);
                    acc[2][1] = fma2(a1q.x, xp.y, acc[2][1]);
                    acc[2][1] = fma2(a2q.x, tq.y, acc[2][1]);
                    acc[3][0] = fma2(a1q.y, xp.x, acc[3][0]);
                    acc[3][0] = fma2(a2q.y, tq.x, acc[3][0]);
                    acc[3][1] = fma2(a1q.y, xp.y, acc[3][1]);
                    acc[3][1] = fma2(a2q.y, tq.y, acc[3][1]);
                }
                __syncthreads();
            }
            float* dw = g_dw + z * WSZ;
            int ii = i0 + tx * 4;
            if (ii + 3 < NIN) {
#pragma unroll
                for (int jm = 0; jm < 4; jm++) {
                    int e = e0 + ty * 4 + jm;
                    if (e < NE) {
                        float2 u0 = upk2(acc[jm][0]);
                        float2 u1 = upk2(acc[jm][1]);
                        *(float4*)&dw[e * NIN + ii] = make_float4(u0.x, u0.y, u1.x, u1.y);
                    }
                }
            }
            __syncthreads();
            if (tid == 0) {
                __threadfence();
                atomicAdd(&g_sflag[z * 32], 1u);
                unsigned old = atomicAdd(&g_wcnt[tile * 8], 1u);
                s_fin = (old % 3u == 2u) ? 1u : 0u;
            }
            __syncthreads();
            if (s_fin) {
                if (tid == 0) __threadfence();   // acquire: see other z partials
                __syncthreads();
                int rrow = tid >> 2;
                int e = e0 + rrow;
                float rs = 0.f;
                if (e < NE) {
                    float sp = g_sc[p * 400 + e];
                    int base = e * NIN;
                    const float* Wold = g_Wbuf + p * WSZ;
                    float* Wnew = g_Wbuf + (p ^ 1) * WSZ;
#pragma unroll
                    for (int c = 0; c < 4; c++) {
                        int jj = i0 + (tid & 3) * 16 + c * 4;
                        if (jj < 781) {
                            float4 w4 = *(const float4*)&Wold[base + jj];
                            float4 d0 = *(const float4*)&g_dw[base + jj];
                            float4 d1 = *(const float4*)&g_dw[WSZ + base + jj];
                            float4 d2 = *(const float4*)&g_dw[2 * WSZ + base + jj];
                            float4 wn;
                            wn.x = fminf(fmaxf(w4.x * sp + d0.x + d1.x + d2.x, 0.f), 1.f);
                            wn.y = fminf(fmaxf(w4.y * sp + d0.y + d1.y + d2.y, 0.f), 1.f);
                            wn.z = fminf(fmaxf(w4.z * sp + d0.z + d1.z + d2.z, 0.f), 1.f);
                            wn.w = fminf(fmaxf(w4.w * sp + d0.w + d1.w + d2.w, 0.f), 1.f);
                            *(float4*)&Wnew[base + jj] = wn;
                            rs += wn.x + wn.y + wn.z + wn.w;
                        }
                    }
                }
                rs += __shfl_down_sync(0xffffffffu, rs, 2);
                rs += __shfl_down_sync(0xffffffffu, rs, 1);
                if ((tid & 3) == 0 && e < NE)
                    g_rsp[(p ^ 1) * 5200 + ix * 400 + e] = rs;
                __syncthreads();
                if (tid == 0) {
                    __threadfence();
                    atomicAdd(&g_wtile[tile * 8], 1u);
                    unsigned o = atomicAdd(&g_wey[ey * 32], 1u);
                    s_is13 = (o % 14u == 12u) ? 1u : 0u;
                }
                __syncthreads();
                if (s_is13) {
                    // 13th finalizer of this ey this step: compute scales for next step
                    if (tid == 0) __threadfence();   // acquire other finalizers' rsp
                    __syncthreads();
                    if (tid < 64) {
                        int ee = e0 + tid;
                        if (ee < NE) {
                            const float* rsn = g_rsp + (p ^ 1) * 5200;
                            float rsum = rsn[ee];
#pragma unroll
                            for (int q = 1; q < 13; q++) rsum += rsn[q * 400 + ee];
                            g_sc[(p ^ 1) * 400 + ee] = 78.4f / rsum;
                        }
                    }
                    __syncthreads();
                    if (tid == 0) { __threadfence(); atomicAdd(&g_wey[ey * 32], 1u); }
                }
            }
        }
    }
}

// ---------------- launch ----------------
extern "C" void kernel_launch(void* const* d_in, const int* in_sizes, int n_in,
                              void* d_out, int out_size) {
    const float* x = nullptr; const float* Wine = nullptr;
    const float* Wei = nullptr; const float* Wie = nullptr;
    for (int i = 0; i < n_in; i++) {
        int sz = in_sizes[i];
        if (sz == TS * BI) x = (const float*)d_in[i];
        else if (sz == WSZ) Wine = (const float*)d_in[i];
        else if (sz == NE * NE) { if (!Wei) Wei = (const float*)d_in[i]; else Wie = (const float*)d_in[i]; }
    }
    float* out = (float*)d_out;
    cudaFuncSetAttribute(k_persist, cudaFuncAttributeMaxDynamicSharedMemorySize, SMEM_BYTES);
    k_persist<<<NBLK, 256, SMEM_BYTES>>>(x, Wei, Wie, Wine, out);
}

// round 16
// speedup vs baseline: 1.1725x; 1.1725x over previous
#include <cuda_runtime.h>

#define TS  50
#define BB  512
#define NE  400
#define NIN 784
#define BE  (BB*NE)
#define BI  (BB*NIN)
#define WSZ (NE*NIN)
#define NBLK 296
#define GZ  5     // gemm1 split-K parts (K=784 -> 160x4,144)
#define SZ  3     // stdp  split-K parts (B=512 -> 176,176,160)
#define NG  280   // G blocks (7e x 8b x 5z)
#define NN  256   // N blocks (512 batches / 2)
#define NS  273   // S blocks (13i x 7e x 3z)

#define WS_STRIDE 164
#define SM_AS     10496            // G: Ws = 64*164 floats, then As 2*1280
#define S_STAGE   4352             // S: one stage = A1(1088)+A2(1088)+X(1088)+T(1088)
#define SMEM_FLOATS 13056
#define SMEM_BYTES  (SMEM_FLOATS*4 + 256)

typedef unsigned long long u64;

// ---------------- f32x2 helpers ----------------
__device__ __forceinline__ u64 fma2(u64 a, u64 b, u64 c) {
    u64 d;
    asm("fma.rn.f32x2 %0, %1, %2, %3;" : "=l"(d) : "l"(a), "l"(b), "l"(c));
    return d;
}
__device__ __forceinline__ u64 pk2(float lo, float hi) {
    u64 r; asm("mov.b64 %0, {%1, %2};" : "=l"(r) : "f"(lo), "f"(hi)); return r;
}
__device__ __forceinline__ float2 upk2(u64 v) {
    float2 u; asm("mov.b64 {%0, %1}, %2;" : "=f"(u.x), "=f"(u.y) : "l"(v)); return u;
}

// ---------------- persistent device state ----------------
__device__ float g_Wbuf[2 * WSZ];          // double-buffered W carry
__device__ float g_rsp[2 * 13 * 400];      // row-sum partials [buf][ix][e]
__device__ float g_sc[2 * 400];            // scale 78.4/rowsum per buf
__device__ float g_dw[SZ * WSZ];
__device__ float g_dg[GZ * BE];            // UNSCALED dg partials
__device__ float g_gine[BE], g_gei[BE], g_gie[BE], g_Iie[BE];
__device__ float g_meme[BE], g_rce[BE], g_memi[BE], g_rci[BE];
__device__ float g_theta[BE], g_tp1[BE], g_tp2[BE];
__device__ float g_a1[BE], g_a2[BE];
__device__ float g_trp[BI];

// ---------------- dataflow flags (cumulative; zeroed in init) ----------------
__device__ unsigned g_gflag[8 * 32];    // per b-tile: G arrivals (35/step)
__device__ unsigned g_nflag[8 * 32];    // per b-tile: N arrivals (32/step)
__device__ unsigned g_sflag[3 * 32];    // per z: S arrivals (91/step)
__device__ unsigned g_wcnt[91 * 8];     // per (ey,ix): S z arrivals (3/step)
__device__ unsigned g_wtile[91 * 8];    // per tile: finalizer done (1/step)
__device__ unsigned g_wey[7 * 32];      // per e-tile: 13 finalizers + 1 scale (14/step)

// ---------------- one-time grid barrier (init only) ----------------
__device__ unsigned g_count;
__device__ unsigned g_gen;
__device__ __forceinline__ void gbar() {
    __syncthreads();
    if (threadIdx.x == 0) {
        __threadfence();
        unsigned gen = *(volatile unsigned*)&g_gen;
        if (atomicAdd(&g_count, 1u) == NBLK - 1) {
            g_count = 0;
            __threadfence();
            *(volatile unsigned*)&g_gen = gen + 1;
        } else {
            while (*(volatile unsigned*)&g_gen == gen) { __nanosleep(40); }
        }
        __threadfence();
    }
    __syncthreads();
}

#define POLL_GE(addr, tgt) do { while (*(volatile unsigned*)(addr) < (tgt)) {} } while (0)

__device__ __forceinline__ void acq() {
    __syncthreads();
    if (threadIdx.x == 0) __threadfence();
    __syncthreads();
}

// ---------------- neuron state update (one e/i pair) ----------------
__device__ __forceinline__ void neuron_update(int idx, float scl, float wei_diag,
                                              float* __restrict__ out, size_t out_off,
                                              float& s_i_out, float& gie_old_out, float& meme_out) {
    float dg = __fmul_rn(g_dg[idx], scl);
#pragma unroll
    for (int z = 1; z < GZ; z++) dg = __fadd_rn(dg, __fmul_rn(g_dg[z * BE + idx], scl));
    float gine = g_gine[idx];
    float meme = g_meme[idx];
    float Iie = g_Iie[idx];
    float Iine = gine * (0.f - meme);                 // E_EE = 0
    gine += (dg - gine) * 0.5f;                        // DT/TAU_SYN_E
    g_gine[idx] = gine;
    float theta = g_theta[idx];
    float thr = -52.f - 20.f + theta;
    float rce = g_rce[idx];
    bool act = (rce <= 0.f);
    if (act) meme += (-65.f - meme + (Iine + Iie)) * 0.005f;   // DT/TAU_MEM_E
    rce = fmaxf(rce - 0.5f, 0.f);
    float s = (act && meme > thr) ? 1.f : 0.f;
    if (s > 0.f) { meme = -65.f; rce = 5.f; }
    g_meme[idx] = meme; g_rce[idx] = rce;
    float dgei = s * wei_diag;
    float gei = g_gei[idx];
    float memi = g_memi[idx];
    float Iei = gei * (0.f - memi);                   // E_EI = 0
    gei += (dgei - gei) * 0.5f;
    g_gei[idx] = gei;
    float rci = g_rci[idx];
    bool acti = (rci <= 0.f);
    if (acti) memi += (-60.f - memi + Iei) * 0.05f;   // DT/TAU_MEM_I
    rci = fmaxf(rci - 0.5f, 0.f);
    float s_i = (acti && memi > -40.f) ? 1.f : 0.f;
    if (s_i > 0.f) { memi = -45.f; rci = 2.f; }
    g_memi[idx] = memi; g_rci[idx] = rci;
    theta = theta * (1.0f - 0.5f / 1e7f) + 0.05f * s;
    g_theta[idx] = theta;
    float tp1 = g_tp1[idx], tp2 = g_tp2[idx];
    float r1 = tp1 * (1.0f - 0.5f / 20.0f);
    float r2 = tp2 * (1.0f - 0.5f / 40.0f);
    bool fired = (s > 0.9f);
    g_tp1[idx] = fired ? 1.f : r1;
    g_tp2[idx] = fired ? 1.f : r2;
    g_a1[idx] = 1e-4f * r1;                           // NU_PRE folded
    g_a2[idx] = fired ? 0.01f * r2 : 0.f;             // NU_POST * spike * ret2
    out[out_off + idx] = s;
    s_i_out = s_i; gie_old_out = g_gie[idx]; meme_out = meme;
}

// ---------------- the single persistent dataflow kernel ----------------
__global__ void __launch_bounds__(256, 2) k_persist(const float* __restrict__ x,
                                                    const float* __restrict__ Wei,
                                                    const float* __restrict__ Wie,
                                                    const float* __restrict__ Wine,
                                                    float* __restrict__ out) {
    extern __shared__ __align__(16) float smem[];
    __shared__ unsigned s_fin, s_is13;
    const int bid = blockIdx.x, tid = threadIdx.x;
    const int gtid = bid * 256 + tid;
    const int sub = tid >> 7;
    const int stid = tid & 127;
    const float4 f4z = make_float4(0.f, 0.f, 0.f, 0.f);

    // ---- INIT ----
    for (int i = gtid; i < WSZ; i += NBLK * 256) {
        g_Wbuf[i] = Wine[i];                       // buffer 0 = Wc(0)
        if (i < BE) {
            g_gine[i] = 0.f; g_gei[i] = 0.f; g_gie[i] = 0.f; g_Iie[i] = 0.f;
            g_meme[i] = -65.f; g_rce[i] = 0.f;
            g_memi[i] = -60.f; g_rci[i] = 0.f;
            g_theta[i] = 20.f; g_tp1[i] = 0.f; g_tp2[i] = 0.f;
        }
        if (i >= 400 && i < 5200) g_rsp[i] = 0.f;  // buf0, ix 1..12 -> 0
        if (i < 8 * 32)  { g_gflag[i] = 0u; g_nflag[i] = 0u; }
        if (i < 3 * 32)  g_sflag[i] = 0u;
        if (i < 91 * 8)  { g_wcnt[i] = 0u; g_wtile[i] = 0u; }
        if (i < 7 * 32)  g_wey[i] = 0u;
    }
    // exact row-sums of Wine -> g_rsp[buf0][ix=0][e] and g_sc[buf0]
    if (bid < 200) {
        int e = bid * 2 + sub;
        float sum = 0.f;
        if (e < NE) {
            const float* row = Wine + e * NIN;
            for (int i = stid; i < NIN; i += 128) sum += row[i];
        }
        for (int o = 16; o > 0; o >>= 1) sum += __shfl_down_sync(0xffffffffu, sum, o);
        if ((tid & 31) == 0) smem[tid >> 5] = sum;
        __syncthreads();
        if (stid == 0 && e < NE) {
            float rs = smem[sub * 4] + smem[sub * 4 + 1] + smem[sub * 4 + 2] + smem[sub * 4 + 3];
            g_rsp[e] = rs;
            g_sc[e] = 78.4f / rs;
        }
    }
    gbar();

    const float wie = Wie[1];    // uniform off-diagonal (17.0)

    for (int t = 0; t < TS; t++) {
        const float* xt = x + (size_t)t * BI;
        const int p = t & 1;
        const unsigned ut = (unsigned)t;

        // ================= G role: dg_z[b,e] = sum_k x[b,k]*Wc[e,k] =================
        if (bid < NG) {
            int z = bid / 56, r = bid % 56;
            int ex = r % 7, by = r / 7;
            int e0 = ex * 64, b0 = by * 64;
            int kz = z * 160;
            int nk = (z == GZ - 1) ? 9 : 10;
            if (tid == 0)  POLL_GE(&g_nflag[by * 32], 32u * ut);
            if (tid == 32) POLL_GE(&g_wey[ex * 32], 14u * ut);
            acq();

            float* Ws = smem;                           // [64][WS_STRIDE]
            float* As = smem + SM_AS;                   // [2][64][20]
            int lrow = tid >> 2, lk4 = (tid & 3) * 4;
            int e = e0 + lrow;
            bool eok = e < NE;
            const float* Wc = g_Wbuf + p * WSZ;
            float4 xreg = *(const float4*)&xt[(b0 + lrow) * NIN + kz + lk4];
#pragma unroll 5
            for (int c = 0; c < nk; c++) {
                int kg = kz + c * 16 + lk4;
                *(float4*)&Ws[lrow * WS_STRIDE + c * 16 + lk4] =
                    eok ? *(const float4*)&Wc[e * NIN + kg] : f4z;
            }

            int tx = tid & 15, ty = tid >> 4;
            u64 acc[4][4];
#pragma unroll
            for (int jm = 0; jm < 4; jm++)
#pragma unroll
                for (int jn = 0; jn < 4; jn++) acc[jm][jn] = 0ULL;

            // single sync per chunk: store -> prefetch -> sync -> compute
            for (int c = 0; c < nk; c++) {
                float* Ab = As + (c & 1) * 1280;
                *(float4*)&Ab[lrow * 20 + lk4] = xreg;
                if (c + 1 < nk)
                    xreg = *(const float4*)&xt[(b0 + lrow) * NIN + kz + (c + 1) * 16 + lk4];
                __syncthreads();       // first iteration also covers the Ws fill
#pragma unroll
                for (int kk = 0; kk < 16; kk += 4) {
                    float4 av[4], bv[4];
#pragma unroll
                    for (int jm = 0; jm < 4; jm++) av[jm] = *(const float4*)&Ab[(ty + 16 * jm) * 20 + kk];
#pragma unroll
                    for (int jn = 0; jn < 4; jn++) bv[jn] = *(const float4*)&Ws[(tx + 16 * jn) * WS_STRIDE + c * 16 + kk];
#pragma unroll
                    for (int jm = 0; jm < 4; jm++) {
                        u64 a0 = pk2(av[jm].x, av[jm].y);
                        u64 a1 = pk2(av[jm].z, av[jm].w);
#pragma unroll
                        for (int jn = 0; jn < 4; jn++) {
                            acc[jm][jn] = fma2(a0, pk2(bv[jn].x, bv[jn].y), acc[jm][jn]);
                            acc[jm][jn] = fma2(a1, pk2(bv[jn].z, bv[jn].w), acc[jm][jn]);
                        }
                    }
                }
            }
            float* dg = g_dg + z * BE;
#pragma unroll
            for (int jn = 0; jn < 4; jn++) {
                int ee = e0 + tx + 16 * jn;
                if (ee < NE) {
#pragma unroll
                    for (int jm = 0; jm < 4; jm++) {
                        float2 u = upk2(acc[jm][jn]);
                        dg[(b0 + ty + 16 * jm) * NE + ee] = u.x + u.y;
                    }
                }
            }
            __syncthreads();
            if (tid == 0) { __threadfence(); atomicAdd(&g_gflag[by * 32], 1u); }
        }

        // ================= N role: neuron dynamics for batches 2bid, 2bid+1 =================
        if (bid < NN) {
            int btile = bid >> 5;
            int zb = (2 * bid < 176) ? 0 : ((2 * bid < 352) ? 1 : 2);
            if (tid < 7) {
                POLL_GE(&g_wey[tid * 32], 14u * ut);
            } else if (tid == 8) {
                POLL_GE(&g_gflag[btile * 32], 35u * (ut + 1u));
            } else if (tid == 9) {
                POLL_GE(&g_sflag[zb * 32], 91u * ut);
            }
            acq();

            const float* sc = g_sc + p * 400;
            int b = bid * 2 + sub;
            float s_i[4], gie_o[4], mem_n[4];
            float ssum = 0.f;
#pragma unroll
            for (int j = 0; j < 4; j++) { s_i[j] = 0.f; gie_o[j] = 0.f; mem_n[j] = 0.f; }
#pragma unroll
            for (int j = 0; j < 4; j++) {
                int e = stid + j * 128;
                if (e < NE) {
                    neuron_update(b * NE + e, sc[e], Wei[e * NE + e], out, (size_t)t * BE,
                                  s_i[j], gie_o[j], mem_n[j]);
                    ssum += s_i[j];
                }
            }
            for (int o = 16; o > 0; o >>= 1) ssum += __shfl_down_sync(0xffffffffu, ssum, o);
            if ((tid & 31) == 0) smem[tid >> 5] = ssum;
            __syncthreads();
            if (tid == 0)   smem[8] = smem[0] + smem[1] + smem[2] + smem[3];
            if (tid == 128) smem[9] = smem[4] + smem[5] + smem[6] + smem[7];
            __syncthreads();
            float S = smem[8 + sub];
#pragma unroll
            for (int j = 0; j < 4; j++) {
                int e = stid + j * 128;
                if (e < NE) {
                    int idx = b * NE + e;
                    float dgie = wie * (S - s_i[j]);
                    g_Iie[idx] = gie_o[j] * (-100.f - mem_n[j]);
                    g_gie[idx] = gie_o[j] + (dgie - gie_o[j]) * 0.25f;
                }
            }
            const float* xr = xt + (size_t)b * NIN;
            float* trp = g_trp + (size_t)b * NIN;
            if (t == 0) {
                for (int i = stid; i < NIN; i += 128) trp[i] = xr[i];
            } else {
                for (int i = stid; i < NIN; i += 128) {
                    float xv = xr[i];
                    trp[i] = (xv > 0.9f) ? 1.f : trp[i] * (1.0f - 0.5f / 20.0f);
                }
            }
            __syncthreads();
            if (tid == 0) { __threadfence(); atomicAdd(&g_nflag[btile * 32], 1u); }
        }

        // ================= S role: dw_z partial + (last z) W finalize =================
        if (bid < NS) {
            int z = bid / 91, r = bid % 91;
            int ix = r % 13, ey = r / 13;
            int tile = ey * 13 + ix;
            int i0 = ix * 64, e0 = ey * 64;
            int bz = z * 176;
            int nkt = (z == SZ - 1) ? 10 : 11;
            const int s_t0 = (z == 0) ? 0 : ((z == 1) ? 2 : 5);
            const int s_tc = (z == 1) ? 4 : 3;
            if (tid < s_tc) {
                POLL_GE(&g_nflag[(s_t0 + tid) * 32], 32u * (ut + 1u));
            } else if (tid == 8) {
                POLL_GE(&g_wtile[tile * 8], ut);
            }
            acq();

            int tx = tid & 15, ty = tid >> 4;
            int lrow = tid >> 4;            // k row 0..15
            int lcol = (tid & 15) * 4;      // column chunk
            bool e_ok = (e0 + lcol + 3) < NE;
            bool i_ok = (i0 + lcol + 3) < NIN;
            u64 acc[4][2];
#pragma unroll
            for (int jm = 0; jm < 4; jm++) { acc[jm][0] = 0ULL; acc[jm][1] = 0ULL; }

            // prefetch chunk 0
            int kb0 = bz + lrow;
            float4 pa1 = e_ok ? *(const float4*)&g_a1[kb0 * NE + e0 + lcol] : f4z;
            float4 pa2 = e_ok ? *(const float4*)&g_a2[kb0 * NE + e0 + lcol] : f4z;
            float4 pxv = i_ok ? *(const float4*)&xt[kb0 * NIN + i0 + lcol] : f4z;
            float4 ptv = i_ok ? *(const float4*)&g_trp[kb0 * NIN + i0 + lcol] : f4z;

            // single sync per chunk, 2-stage smem
            for (int kt = 0; kt < nkt; kt++) {
                float* stg = smem + (kt & 1) * S_STAGE;
                *(float4*)&stg[lrow * 68 + lcol]        = pa1;   // A1
                *(float4*)&stg[1088 + lrow * 68 + lcol] = pa2;   // A2
                *(float4*)&stg[2176 + lrow * 68 + lcol] = pxv;   // X
                *(float4*)&stg[3264 + lrow * 68 + lcol] = ptv;   // T
                if (kt + 1 < nkt) {
                    int kb = bz + (kt + 1) * 16 + lrow;
                    pa1 = e_ok ? *(const float4*)&g_a1[kb * NE + e0 + lcol] : f4z;
                    pa2 = e_ok ? *(const float4*)&g_a2[kb * NE + e0 + lcol] : f4z;
                    pxv = i_ok ? *(const float4*)&xt[kb * NIN + i0 + lcol] : f4z;
                    ptv = i_ok ? *(const float4*)&g_trp[kb * NIN + i0 + lcol] : f4z;
                }
                __syncthreads();
                const float* A1s = stg;
                const float* A2s = stg + 1088;
                const float* Xs  = stg + 2176;
                const float* Ts  = stg + 3264;
#pragma unroll
                for (int k = 0; k < 16; k++) {
                    float4 a1v = *(const float4*)&A1s[k * 68 + ty * 4];
                    float4 a2v = *(const float4*)&A2s[k * 68 + ty * 4];
                    float4 xv  = *(const float4*)&Xs[k * 68 + tx * 4];
                    float4 tv  = *(const float4*)&Ts[k * 68 + tx * 4];
                    u64 xp0 = pk2(xv.x, xv.y), xp1 = pk2(xv.z, xv.w);
                    u64 tq0 = pk2(tv.x, tv.y), tq1 = pk2(tv.z, tv.w);
                    float a1a[4] = {a1v.x, a1v.y, a1v.z, a1v.w};
                    float a2a[4] = {a2v.x, a2v.y, a2v.z, a2v.w};
#pragma unroll
                    for (int jm = 0; jm < 4; jm++) {
                        u64 a1b = pk2(a1a[jm], a1a[jm]);
                        u64 a2b = pk2(a2a[jm], a2a[jm]);
                        acc[jm][0] = fma2(a1b, xp0, acc[jm][0]);
                        acc[jm][0] = fma2(a2b, tq0, acc[jm][0]);
                        acc[jm][1] = fma2(a1b, xp1, acc[jm][1]);
                        acc[jm][1] = fma2(a2b, tq1, acc[jm][1]);
                    }
                }
            }
            float* dw = g_dw + z * WSZ;
            int ii = i0 + tx * 4;
            if (ii + 3 < NIN) {
#pragma unroll
                for (int jm = 0; jm < 4; jm++) {
                    int e = e0 + ty * 4 + jm;
                    if (e < NE) {
                        float2 u0 = upk2(acc[jm][0]);
                        float2 u1 = upk2(acc[jm][1]);
                        *(float4*)&dw[e * NIN + ii] = make_float4(u0.x, u0.y, u1.x, u1.y);
                    }
                }
            }
            __syncthreads();
            if (tid == 0) {
                __threadfence();
                atomicAdd(&g_sflag[z * 32], 1u);
                unsigned old = atomicAdd(&g_wcnt[tile * 8], 1u);
                s_fin = (old % 3u == 2u) ? 1u : 0u;
            }
            __syncthreads();
            if (s_fin) {
                if (tid == 0) __threadfence();   // acquire: see other z partials
                __syncthreads();
                int rrow = tid >> 2;
                int e = e0 + rrow;
                float rs = 0.f;
                if (e < NE) {
                    float sp = g_sc[p * 400 + e];
                    int base = e * NIN;
                    const float* Wold = g_Wbuf + p * WSZ;
                    float* Wnew = g_Wbuf + (p ^ 1) * WSZ;
#pragma unroll
                    for (int c = 0; c < 4; c++) {
                        int jj = i0 + (tid & 3) * 16 + c * 4;
                        if (jj < 781) {
                            float4 w4 = *(const float4*)&Wold[base + jj];
                            float4 d0 = *(const float4*)&g_dw[base + jj];
                            float4 d1 = *(const float4*)&g_dw[WSZ + base + jj];
                            float4 d2 = *(const float4*)&g_dw[2 * WSZ + base + jj];
                            float4 wn;
                            wn.x = fminf(fmaxf(w4.x * sp + d0.x + d1.x + d2.x, 0.f), 1.f);
                            wn.y = fminf(fmaxf(w4.y * sp + d0.y + d1.y + d2.y, 0.f), 1.f);
                            wn.z = fminf(fmaxf(w4.z * sp + d0.z + d1.z + d2.z, 0.f), 1.f);
                            wn.w = fminf(fmaxf(w4.w * sp + d0.w + d1.w + d2.w, 0.f), 1.f);
                            *(float4*)&Wnew[base + jj] = wn;
                            rs += wn.x + wn.y + wn.z + wn.w;
                        }
                    }
                }
                rs += __shfl_down_sync(0xffffffffu, rs, 2);
                rs += __shfl_down_sync(0xffffffffu, rs, 1);
                if ((tid & 3) == 0 && e < NE)
                    g_rsp[(p ^ 1) * 5200 + ix * 400 + e] = rs;
                __syncthreads();
                if (tid == 0) {
                    __threadfence();
                    atomicAdd(&g_wtile[tile * 8], 1u);
                    unsigned o = atomicAdd(&g_wey[ey * 32], 1u);
                    s_is13 = (o % 14u == 12u) ? 1u : 0u;
                }
                __syncthreads();
                if (s_is13) {
                    // 13th finalizer of this ey this step: compute scales for next step
                    if (tid == 0) __threadfence();   // acquire other finalizers' rsp
                    __syncthreads();
                    if (tid < 64) {
                        int ee = e0 + tid;
                        if (ee < NE) {
                            const float* rsn = g_rsp + (p ^ 1) * 5200;
                            float rsum = rsn[ee];
#pragma unroll
                            for (int q = 1; q < 13; q++) rsum += rsn[q * 400 + ee];
                            g_sc[(p ^ 1) * 400 + ee] = 78.4f / rsum;
                        }
                    }
                    __syncthreads();
                    if (tid == 0) { __threadfence(); atomicAdd(&g_wey[ey * 32], 1u); }
                }
            }
        }
    }
}

// ---------------- launch ----------------
extern "C" void kernel_launch(void* const* d_in, const int* in_sizes, int n_in,
                              void* d_out, int out_size) {
    const float* x = nullptr; const float* Wine = nullptr;
    const float* Wei = nullptr; const float* Wie = nullptr;
    for (int i = 0; i < n_in; i++) {
        int sz = in_sizes[i];
        if (sz == TS * BI) x = (const float*)d_in[i];
        else if (sz == WSZ) Wine = (const float*)d_in[i];
        else if (sz == NE * NE) { if (!Wei) Wei = (const float*)d_in[i]; else Wie = (const float*)d_in[i]; }
    }
    float* out = (float*)d_out;
    cudaFuncSetAttribute(k_persist, cudaFuncAttributeMaxDynamicSharedMemorySize, SMEM_BYTES);
    k_persist<<<NBLK, 256, SMEM_BYTES>>>(x, Wei, Wie, Wine, out);
}